// round 4
// baseline (speedup 1.0000x reference)
#include <cuda_runtime.h>
#include <cuda_bf16.h>

#define NSP 8192
#define NR  2097152

// metadata order:
// 0 abundances[8192] f32, 1 temperature, 2 cr_rate, 3 fuv_rate,
// 4 alpha[NR], 5 beta[NR], 6 gamma[NR], 7 rtype[NR] i32,
// 8 react_species[NR,2] i32, 9 inc_rows[4*NR] i32,
// 10 inc_cols (structurally repeat(arange(NR),4) -- unused),
// 11 inc_vals (structurally -1,-1,+1,+1 per reaction -- unused), 12 n_species

__device__ __forceinline__ float ex2_approx(float x) {
    float y;
    asm("ex2.approx.ftz.f32 %0, %1;" : "=f"(y) : "f"(x));
    return y;
}

__global__ void zero_out_kernel(float* __restrict__ out, int n) {
    int i = blockIdx.x * blockDim.x + threadIdx.x;
    if (i < n) out[i] = 0.0f;
}

__global__ __launch_bounds__(1024, 2)
void rates_scatter_kernel(
    const float* __restrict__ abund,
    const float* __restrict__ Tptr,
    const float* __restrict__ crptr,
    const float* __restrict__ fuvptr,
    const float* __restrict__ alpha,
    const float* __restrict__ beta,
    const float* __restrict__ gamma,
    const int*   __restrict__ rtype,
    const int2*  __restrict__ rspec,   // [NR] reactant pairs
    const int4*  __restrict__ rows4,   // [NR] incidence-row quads
    float* __restrict__ out)
{
    extern __shared__ float smem[];
    float* acc = smem;          // [NSP] per-CTA accumulator (reactant terms)
    float* sab = smem + NSP;    // [NSP] staged abundances

    for (int i = threadIdx.x; i < NSP; i += blockDim.x) {
        acc[i] = 0.0f;
        sab[i] = abund[i];
    }
    __syncthreads();

    const float T   = *Tptr;
    const float cr  = *crptr;
    const float fuv = *fuvptr;
    const float L2E = 1.4426950408889634f;           // log2(e)
    const float c1  = __log2f(T * (1.0f / 300.0f));  // log2(T/300)
    const float c2  = -L2E / T;                      // exp(-g/T) = exp2(g*c2)

    const int stride  = gridDim.x * blockDim.x;
    const int stride2 = 2 * stride;
    const int tid0    = blockIdx.x * blockDim.x + threadIdx.x;

    for (int r0 = tid0; r0 < NR; r0 += stride2) {
        const int r1 = r0 + stride;
        const bool has2 = (r1 < NR);

        // Batched independent scalar-pattern loads (all 1-wf-per-warp coalesced)
        const float a0 = alpha[r0];
        const float b0 = beta[r0];
        const float g0 = gamma[r0];
        const int   t0 = rtype[r0];
        const int2  sp0 = rspec[r0];
        const int4  rw0 = rows4[r0];

        float a1 = 0.f, b1 = 0.f, g1 = 0.f;
        int   t1 = 1;
        int2  sp1 = make_int2(0, 0);
        int4  rw1 = make_int4(0, 0, 0, 0);
        if (has2) {
            a1 = alpha[r1]; b1 = beta[r1]; g1 = gamma[r1]; t1 = rtype[r1];
            sp1 = rspec[r1]; rw1 = rows4[r1];
        }

        // reaction r0
        {
            const float e  = (t0 == 0) ? fmaf(b0, c1, g0 * c2) : (-g0 * L2E);
            const float ex = ex2_approx(e);
            float k;
            if (t0 == 1)      k = a0 * cr;
            else if (t0 == 2) k = a0 * fuv * ex;
            else              k = a0 * ex;
            k *= sab[sp0.x] * sab[sp0.y];

            atomicAdd(&acc[rw0.x], -k);        // smem pipe
            atomicAdd(&acc[rw0.y], -k);
            atomicAdd(&out[rw0.z],  k);        // L2 atomic pipe (no-return REDG)
            atomicAdd(&out[rw0.w],  k);
        }
        // reaction r1
        if (has2) {
            const float e  = (t1 == 0) ? fmaf(b1, c1, g1 * c2) : (-g1 * L2E);
            const float ex = ex2_approx(e);
            float k;
            if (t1 == 1)      k = a1 * cr;
            else if (t1 == 2) k = a1 * fuv * ex;
            else              k = a1 * ex;
            k *= sab[sp1.x] * sab[sp1.y];

            atomicAdd(&acc[rw1.x], -k);
            atomicAdd(&acc[rw1.y], -k);
            atomicAdd(&out[rw1.z],  k);
            atomicAdd(&out[rw1.w],  k);
        }
    }

    __syncthreads();
    // Flush reactant accumulator; rotate start per CTA to decorrelate L2 targets.
    const int rot = (blockIdx.x * 61) & (NSP - 1);
    for (int i = threadIdx.x; i < NSP; i += blockDim.x) {
        const int j = (i + rot) & (NSP - 1);
        atomicAdd(&out[j], acc[j]);
    }
}

extern "C" void kernel_launch(void* const* d_in, const int* in_sizes, int n_in,
                              void* d_out, int out_size) {
    const float* abund  = (const float*)d_in[0];
    const float* T      = (const float*)d_in[1];
    const float* crr    = (const float*)d_in[2];
    const float* fuvr   = (const float*)d_in[3];
    float* out = (float*)d_out;

    const int smem_bytes = 2 * NSP * sizeof(float);  // 64 KB
    cudaFuncSetAttribute(rates_scatter_kernel,
                         cudaFuncAttributeMaxDynamicSharedMemorySize, smem_bytes);

    zero_out_kernel<<<(out_size + 255) / 256, 256>>>(out, out_size);

    rates_scatter_kernel<<<296, 1024, smem_bytes>>>(
        abund, T, crr, fuvr,
        (const float*)d_in[4], (const float*)d_in[5], (const float*)d_in[6],
        (const int*)d_in[7], (const int2*)d_in[8], (const int4*)d_in[9],
        out);
}

// round 5
// speedup vs baseline: 3.7869x; 3.7869x over previous
#include <cuda_runtime.h>
#include <cuda_bf16.h>

#define NSP 8192
#define NR  2097152

// metadata order:
// 0 abundances[8192] f32, 1 temperature, 2 cr_rate, 3 fuv_rate,
// 4 alpha[NR], 5 beta[NR], 6 gamma[NR], 7 rtype[NR] i32,
// 8 react_species[NR,2] i32, 9 inc_rows[4*NR] i32,
// 10 inc_cols (structurally repeat(arange(NR),4) -- unused),
// 11 inc_vals (structurally -1,-1,+1,+1 per reaction -- unused), 12 n_species

__device__ __forceinline__ float ex2_approx(float x) {
    float y;
    asm("ex2.approx.ftz.f32 %0, %1;" : "=f"(y) : "f"(x));
    return y;
}

__global__ void zero_out_kernel(float* __restrict__ out, int n) {
    int i = blockIdx.x * blockDim.x + threadIdx.x;
    if (i < n) out[i] = 0.0f;
}

struct Rxn {
    float a, b, g;
    int   t;
    int2  sp;
    int4  rw;
};

__global__ __launch_bounds__(512, 2)
void rates_scatter_kernel(
    const float* __restrict__ abund,
    const float* __restrict__ Tptr,
    const float* __restrict__ crptr,
    const float* __restrict__ fuvptr,
    const float* __restrict__ alpha,
    const float* __restrict__ beta,
    const float* __restrict__ gamma,
    const int*   __restrict__ rtype,
    const int2*  __restrict__ rspec,   // [NR] reactant pairs
    const int4*  __restrict__ rows4,   // [NR] incidence-row quads
    float* __restrict__ out)
{
    extern __shared__ float smem[];
    float* acc = smem;          // [NSP] per-CTA accumulator
    float* sab = smem + NSP;    // [NSP] staged abundances (LDS gathers)

    for (int i = threadIdx.x; i < NSP; i += blockDim.x) {
        acc[i] = 0.0f;
        sab[i] = abund[i];
    }
    __syncthreads();

    const float T   = *Tptr;
    const float cr  = *crptr;
    const float fuv = *fuvptr;
    const float L2E = 1.4426950408889634f;           // log2(e)
    const float c1  = __log2f(T * (1.0f / 300.0f));  // log2(T/300)
    const float c2  = -L2E / T;                      // exp(-g/T) = exp2(g*c2)

    const int stride = gridDim.x * blockDim.x;
    int r = blockIdx.x * blockDim.x + threadIdx.x;

    Rxn cur;
    if (r < NR) {
        cur.a = alpha[r]; cur.b = beta[r]; cur.g = gamma[r];
        cur.t = rtype[r]; cur.sp = rspec[r]; cur.rw = rows4[r];
    }

    while (r < NR) {
        const int rn = r + stride;

        // ---- prefetch next iteration's streaming loads (hide DRAM latency) ----
        Rxn nxt;
        if (rn < NR) {
            nxt.a = alpha[rn]; nxt.b = beta[rn]; nxt.g = gamma[rn];
            nxt.t = rtype[rn]; nxt.sp = rspec[rn]; nxt.rw = rows4[rn];
        }

        // ---- process current reaction ----
        {
            const float e  = (cur.t == 0) ? fmaf(cur.b, c1, cur.g * c2)
                                          : (-cur.g * L2E);
            const float ex = ex2_approx(e);
            float k;
            if (cur.t == 1)      k = cur.a * cr;
            else if (cur.t == 2) k = cur.a * fuv * ex;
            else                 k = cur.a * ex;

            k *= sab[cur.sp.x] * sab[cur.sp.y];   // LDS gathers

            atomicAdd(&acc[cur.rw.x], -k);
            atomicAdd(&acc[cur.rw.y], -k);
            atomicAdd(&acc[cur.rw.z],  k);
            atomicAdd(&acc[cur.rw.w],  k);
        }

        cur = nxt;
        r = rn;
    }

    __syncthreads();
    for (int i = threadIdx.x; i < NSP; i += blockDim.x)
        atomicAdd(&out[i], acc[i]);   // no-return -> REDG, once per CTA
}

extern "C" void kernel_launch(void* const* d_in, const int* in_sizes, int n_in,
                              void* d_out, int out_size) {
    const float* abund  = (const float*)d_in[0];
    const float* T      = (const float*)d_in[1];
    const float* crr    = (const float*)d_in[2];
    const float* fuvr   = (const float*)d_in[3];
    float* out = (float*)d_out;

    const int smem_bytes = 2 * NSP * sizeof(float);  // 64 KB
    cudaFuncSetAttribute(rates_scatter_kernel,
                         cudaFuncAttributeMaxDynamicSharedMemorySize, smem_bytes);

    zero_out_kernel<<<(out_size + 255) / 256, 256>>>(out, out_size);

    rates_scatter_kernel<<<296, 512, smem_bytes>>>(
        abund, T, crr, fuvr,
        (const float*)d_in[4], (const float*)d_in[5], (const float*)d_in[6],
        (const int*)d_in[7], (const int2*)d_in[8], (const int4*)d_in[9],
        out);
}

// round 6
// speedup vs baseline: 3.8227x; 1.0095x over previous
#include <cuda_runtime.h>
#include <cuda_bf16.h>
#include <cstdint>

#define NSP 8192
#define NR  2097152
#define TILE 1024
#define NTILES (NR / TILE)      // 2048, exact
#define NCTA 148

// Per-tile staging buffer layout (bytes), 40960 total
#define BUF_BYTES 40960
#define OFF_A   0        // alpha  [TILE] f32   4KB
#define OFF_B   4096     // beta   [TILE] f32   4KB
#define OFF_G   8192     // gamma  [TILE] f32   4KB
#define OFF_T   12288    // rtype  [TILE] i32   4KB
#define OFF_SP  16384    // rspec  [TILE] int2  8KB
#define OFF_RW  24576    // rows   [TILE] int4 16KB

// Shared memory layout
#define SOFF_SAB  0
#define SOFF_ACC  32768
#define SOFF_BUF0 65536
#define SOFF_BUF1 (65536 + BUF_BYTES)
#define SOFF_MBAR (65536 + 2 * BUF_BYTES)
#define SMEM_TOTAL (SOFF_MBAR + 64)

__device__ __forceinline__ float ex2_approx(float x) {
    float y;
    asm("ex2.approx.ftz.f32 %0, %1;" : "=f"(y) : "f"(x));
    return y;
}

__device__ __forceinline__ uint32_t smem_u32(const void* p) {
    uint32_t a;
    asm("{ .reg .u64 t; cvta.to.shared.u64 t, %1; cvt.u32.u64 %0, t; }"
        : "=r"(a) : "l"(p));
    return a;
}

__device__ __forceinline__ void bulk_copy(uint32_t dst_smem, const void* src,
                                          uint32_t bytes, uint32_t mbar) {
    asm volatile(
        "cp.async.bulk.shared::cluster.global.mbarrier::complete_tx::bytes "
        "[%0], [%1], %2, [%3];"
        :: "r"(dst_smem), "l"(src), "r"(bytes), "r"(mbar) : "memory");
}

__device__ __forceinline__ void mbar_init(uint32_t mbar, uint32_t count) {
    asm volatile("mbarrier.init.shared.b64 [%0], %1;" :: "r"(mbar), "r"(count) : "memory");
}

__device__ __forceinline__ void mbar_expect_tx(uint32_t mbar, uint32_t tx) {
    asm volatile("mbarrier.arrive.expect_tx.shared.b64 _, [%0], %1;"
                 :: "r"(mbar), "r"(tx) : "memory");
}

__device__ __forceinline__ void mbar_wait(uint32_t mbar, uint32_t parity) {
    asm volatile(
        "{\n\t"
        ".reg .pred P;\n\t"
        "WL_%=:\n\t"
        "mbarrier.try_wait.parity.acquire.cta.shared::cta.b64 P, [%0], %1, 0x989680;\n\t"
        "@P bra.uni WD_%=;\n\t"
        "bra.uni WL_%=;\n\t"
        "WD_%=:\n\t"
        "}"
        :: "r"(mbar), "r"(parity) : "memory");
}

__global__ void zero_out_kernel(float* __restrict__ out, int n) {
    int i = blockIdx.x * blockDim.x + threadIdx.x;
    if (i < n) out[i] = 0.0f;
}

__global__ __launch_bounds__(1024, 1)
void rates_scatter_kernel(
    const float* __restrict__ abund,
    const float* __restrict__ Tptr,
    const float* __restrict__ crptr,
    const float* __restrict__ fuvptr,
    const float* __restrict__ alpha,
    const float* __restrict__ beta,
    const float* __restrict__ gamma,
    const int*   __restrict__ rtype,
    const int2*  __restrict__ rspec,
    const int4*  __restrict__ rows4,
    float* __restrict__ out)
{
    extern __shared__ char smem[];
    float* sab = (float*)(smem + SOFF_SAB);
    float* acc = (float*)(smem + SOFF_ACC);
    const uint32_t smem_base = smem_u32(smem);
    const uint32_t mbar0 = smem_base + SOFF_MBAR;
    const uint32_t mbar1 = smem_base + SOFF_MBAR + 8;
    const uint32_t buf_s[2] = { smem_base + SOFF_BUF0, smem_base + SOFF_BUF1 };

    const int tid = threadIdx.x;
    for (int i = tid; i < NSP; i += blockDim.x) {
        sab[i] = abund[i];
        acc[i] = 0.0f;
    }
    if (tid == 0) {
        mbar_init(mbar0, 1);
        mbar_init(mbar1, 1);
    }
    __syncthreads();

    const float T   = *Tptr;
    const float cr  = *crptr;
    const float fuv = *fuvptr;
    const float L2E = 1.4426950408889634f;
    const float c1  = __log2f(T * (1.0f / 300.0f));
    const float c2  = -L2E / T;

    // Tile n for this CTA covers reactions [r0, r0+TILE), r0 = (cta + n*NCTA)*TILE
    const int cta = blockIdx.x;
    const int my_ntiles = (NTILES - cta + NCTA - 1) / NCTA;

    auto issue_tile = [&](int n, int buf) {
        const long r0 = (long)(cta + n * NCTA) * TILE;
        const uint32_t mb = buf ? mbar1 : mbar0;
        const uint32_t bs = buf_s[buf];
        mbar_expect_tx(mb, BUF_BYTES);
        bulk_copy(bs + OFF_A,  alpha + r0,  TILE * 4,  mb);
        bulk_copy(bs + OFF_B,  beta + r0,   TILE * 4,  mb);
        bulk_copy(bs + OFF_G,  gamma + r0,  TILE * 4,  mb);
        bulk_copy(bs + OFF_T,  rtype + r0,  TILE * 4,  mb);
        bulk_copy(bs + OFF_SP, rspec + r0,  TILE * 8,  mb);
        bulk_copy(bs + OFF_RW, rows4 + r0,  TILE * 16, mb);
    };

    if (tid == 0 && my_ntiles > 0) issue_tile(0, 0);

    int ph[2] = {0, 0};
    for (int n = 0; n < my_ntiles; n++) {
        const int buf = n & 1;

        // Prefetch next tile into the other buffer (free since iter n-1's sync)
        if (tid == 0 && (n + 1) < my_ntiles) issue_tile(n + 1, buf ^ 1);

        mbar_wait(buf ? mbar1 : mbar0, ph[buf]);
        ph[buf] ^= 1;

        // One reaction per thread, all param reads are conflict-free LDS
        char* b = smem + (buf ? SOFF_BUF1 : SOFF_BUF0);
        const float a  = ((const float*)(b + OFF_A))[tid];
        const float bb = ((const float*)(b + OFF_B))[tid];
        const float g  = ((const float*)(b + OFF_G))[tid];
        const int   t  = ((const int*)(b + OFF_T))[tid];
        const int2  sp = ((const int2*)(b + OFF_SP))[tid];
        const int4  rw = ((const int4*)(b + OFF_RW))[tid];

        const float e  = (t == 0) ? fmaf(bb, c1, g * c2) : (-g * L2E);
        const float ex = ex2_approx(e);
        float k;
        if (t == 1)      k = a * cr;
        else if (t == 2) k = a * fuv * ex;
        else             k = a * ex;

        k *= sab[sp.x] * sab[sp.y];

        atomicAdd(&acc[rw.x], -k);
        atomicAdd(&acc[rw.y], -k);
        atomicAdd(&acc[rw.z],  k);
        atomicAdd(&acc[rw.w],  k);

        __syncthreads();   // buffer `buf` fully consumed -> reusable at n+2
    }

    for (int i = tid; i < NSP; i += blockDim.x)
        atomicAdd(&out[i], acc[i]);
}

extern "C" void kernel_launch(void* const* d_in, const int* in_sizes, int n_in,
                              void* d_out, int out_size) {
    const float* abund  = (const float*)d_in[0];
    const float* T      = (const float*)d_in[1];
    const float* crr    = (const float*)d_in[2];
    const float* fuvr   = (const float*)d_in[3];
    float* out = (float*)d_out;

    cudaFuncSetAttribute(rates_scatter_kernel,
                         cudaFuncAttributeMaxDynamicSharedMemorySize, SMEM_TOTAL);

    zero_out_kernel<<<(out_size + 255) / 256, 256>>>(out, out_size);

    rates_scatter_kernel<<<NCTA, 1024, SMEM_TOTAL>>>(
        abund, T, crr, fuvr,
        (const float*)d_in[4], (const float*)d_in[5], (const float*)d_in[6],
        (const int*)d_in[7], (const int2*)d_in[8], (const int4*)d_in[9],
        out);
}